// round 16
// baseline (speedup 1.0000x reference)
#include <cuda_runtime.h>
#include <cuda_fp16.h>
#include <cstdint>
#include <math.h>

// Problem constants
#define BATCH 2
#define DMODEL 1024
#define SEQ 2048
#define HEADS 16
#define HDIM 64

// Scratch (allocation-free rule: __device__ globals)
__device__ float g_Q[BATCH * DMODEL * SEQ];
__device__ float g_K[BATCH * DMODEL * SEQ];
__device__ float g_V[BATCH * DMODEL * SEQ];
__device__ float g_X[BATCH * DMODEL * SEQ];

// ===========================================================================
// Helpers
// ===========================================================================
__device__ __forceinline__ uint32_t pack_h2(float lo, float hi) {
    __half2 h = __floats2half2_rn(lo, hi);
    return *reinterpret_cast<uint32_t*>(&h);
}

// D += A * B  (m16n8k16, fp16 inputs, fp32 accum). A row-major, B "col".
__device__ __forceinline__ void mma_f16(float d[4], const uint32_t a[4],
                                        uint32_t b0, uint32_t b1) {
    asm volatile(
        "mma.sync.aligned.m16n8k16.row.col.f32.f16.f16.f32 "
        "{%0,%1,%2,%3}, {%4,%5,%6,%7}, {%8,%9}, {%0,%1,%2,%3};\n"
        : "+f"(d[0]), "+f"(d[1]), "+f"(d[2]), "+f"(d[3])
        : "r"(a[0]), "r"(a[1]), "r"(a[2]), "r"(a[3]), "r"(b0), "r"(b1));
}

// ===========================================================================
// GEMM v4 (fp16 m16n8k16), single batch slice: C[m][n] = A[m][:]·X[:][n]+bias
// X and C are pre-offset by the host for the batch. Grid (16, 8, 1).
// ===========================================================================
#define AP16 36
#define BP16 136

__global__ __launch_bounds__(256, 2) void gemm_mma_h(
    const float* __restrict__ A, const float* __restrict__ Xb,
    const float* __restrict__ bias, float* __restrict__ Cb)
{
    __shared__ uint32_t As[128 * AP16];
    __shared__ uint32_t Bs[32 * BP16];

    const int tid = threadIdx.x;
    const int lane = tid & 31;
    const int wid = tid >> 5;
    const int wm = (wid >> 2) * 64;
    const int wn = (wid & 3) * 32;
    const int r = lane >> 2, c = lane & 3;
    const int row0 = blockIdx.y * 128, col0 = blockIdx.x * 128;

    float acc[4][4][4];
#pragma unroll
    for (int mt = 0; mt < 4; mt++)
#pragma unroll
        for (int nt = 0; nt < 4; nt++)
#pragma unroll
            for (int i = 0; i < 4; i++) acc[mt][nt][i] = 0.f;

    for (int kt = 0; kt < DMODEL / 64; ++kt) {
        const int k0 = kt * 64;
        __syncthreads();
        // ---- A tile: 128 m x 64 k -> As[m][32 kp] ----
#pragma unroll
        for (int it = 0; it < 8; ++it) {
            int id = tid + it * 256;
            int m = id >> 4;
            int k4 = (id & 15) << 2;
            float4 v = *(const float4*)(A + (size_t)(row0 + m) * DMODEL + k0 + k4);
            int kp0 = (id & 15) << 1;
            As[m * AP16 + kp0]     = pack_h2(v.x, v.y);
            As[m * AP16 + kp0 + 1] = pack_h2(v.z, v.w);
        }
        // ---- B tile: 64 k x 128 n -> Bs[32 kp][128 n] ----
#pragma unroll
        for (int it = 0; it < 4; ++it) {
            int id = tid + it * 256;
            int kp = id >> 5;
            int n4 = (id & 31) << 2;
            const float* x0 = Xb + (size_t)(k0 + 2 * kp) * SEQ + col0 + n4;
            float4 va = *(const float4*)x0;
            float4 vb = *(const float4*)(x0 + SEQ);
            Bs[kp * BP16 + n4 + 0] = pack_h2(va.x, vb.x);
            Bs[kp * BP16 + n4 + 1] = pack_h2(va.y, vb.y);
            Bs[kp * BP16 + n4 + 2] = pack_h2(va.z, vb.z);
            Bs[kp * BP16 + n4 + 3] = pack_h2(va.w, vb.w);
        }
        __syncthreads();

#pragma unroll
        for (int ks = 0; ks < 4; ++ks) {
            uint32_t af[4][4], bf[4][2];
#pragma unroll
            for (int mt = 0; mt < 4; ++mt) {
                int mr = wm + mt * 16 + r;
                af[mt][0] = As[mr * AP16 + ks * 8 + c];
                af[mt][1] = As[(mr + 8) * AP16 + ks * 8 + c];
                af[mt][2] = As[mr * AP16 + ks * 8 + c + 4];
                af[mt][3] = As[(mr + 8) * AP16 + ks * 8 + c + 4];
            }
#pragma unroll
            for (int nt = 0; nt < 4; ++nt) {
                int nc = wn + nt * 8 + r;
                bf[nt][0] = Bs[(ks * 8 + c) * BP16 + nc];
                bf[nt][1] = Bs[(ks * 8 + c + 4) * BP16 + nc];
            }
#pragma unroll
            for (int mt = 0; mt < 4; ++mt)
#pragma unroll
                for (int nt = 0; nt < 4; ++nt)
                    mma_f16(acc[mt][nt], af[mt], bf[nt][0], bf[nt][1]);
        }
    }

#pragma unroll
    for (int mt = 0; mt < 4; ++mt) {
        int r0 = row0 + wm + mt * 16 + r;
        float bv0 = __ldg(bias + r0);
        float bv1 = __ldg(bias + r0 + 8);
#pragma unroll
        for (int nt = 0; nt < 4; ++nt) {
            int c0 = col0 + wn + nt * 8 + c * 2;
            float2 v0 = make_float2(acc[mt][nt][0] + bv0, acc[mt][nt][1] + bv0);
            float2 v1 = make_float2(acc[mt][nt][2] + bv1, acc[mt][nt][3] + bv1);
            *(float2*)(Cb + (size_t)r0 * SEQ + c0) = v0;
            *(float2*)(Cb + (size_t)(r0 + 8) * SEQ + c0) = v1;
        }
    }
}

// ===========================================================================
// Flash attention v3 (R14 math verbatim), single batch slice:
// Q/K/V/O pre-offset by b*DMODEL*SEQ; grid (16 qtiles, 16 heads).
// ===========================================================================
#define QF_OFF 0
#define KF_OFF 4096
#define VF_OFF 6144
#define ATTN_SMEM_B (8448 * 4)
#define XPITCH 132
#define QSCALE 0.1803368801111204f   // 0.125 * log2(e)

__global__ __launch_bounds__(128, 2) void attn_mma3(
    const float* __restrict__ Q, const float* __restrict__ K,
    const float* __restrict__ V, float* __restrict__ O)
{
    extern __shared__ uint32_t sm[];

    const int tid = threadIdx.x;
    const int lane = tid & 31, wid = tid >> 5;
    const int r = lane >> 2, c = lane & 3;
    const int lsw = lane ^ ((lane >> 3) & 3);

    const int h = blockIdx.y;
    const int n0 = blockIdx.x * 128;
    const size_t base = (size_t)h * SEQ;
    const size_t ds = (size_t)HEADS * SEQ;

    // ---------------- Stage Q (fp16x2 A-fragment-major, scaled) ------------
    {
        const int q_dp = tid >> 2;
        const int cQ = q_dp & 3, ahalf = (q_dp >> 2) & 1, kcQ = q_dp >> 3;
        const float* q0 = Q + base + (size_t)(2 * q_dp) * ds + n0;
        const float* q1 = q0 + ds;
#pragma unroll
        for (int it = 0; it < 8; ++it) {
            int qg = ((tid & 3) + it * 4) * 4;
            float4 va = *(const float4*)(q0 + qg);
            float4 vb = *(const float4*)(q1 + qg);
            float fa[4] = {va.x, va.y, va.z, va.w};
            float fb[4] = {vb.x, vb.y, vb.z, vb.w};
#pragma unroll
            for (int e = 0; e < 4; ++e) {
                int qloc = qg + e;
                int wq = qloc >> 5, mtq = (qloc >> 4) & 1;
                int rhq = (qloc >> 3) & 1, rQ = qloc & 7;
                int lq = rQ * 4 + cQ;
                int lsq = lq ^ ((lq >> 3) & 3);
                sm[QF_OFF + wq * 1024 + (mtq * 4 + kcQ) * 128 + lsq * 4
                   + rhq + 2 * ahalf] = pack_h2(fa[e] * QSCALE, fb[e] * QSCALE);
            }
        }
    }

    const int k_dp = tid >> 2;
    const int cK = k_dp & 3, kwh = (k_dp >> 2) & 1, kcK = k_dp >> 3;
    const float* kb0 = K + base + (size_t)(2 * k_dp) * ds;
    const float* kb1 = kb0 + ds;

    const int sd0 = tid >> 4;
    const int sj0 = (tid & 15) * 4;
    const float* vbase = V + base + (size_t)sd0 * ds + sj0;
    const int jp0 = sj0 >> 1;
    const int kcV = jp0 >> 3, jplV = jp0 & 7;
    const int cV = jplV & 3, vwh = (jplV >> 2) & 1;
    const int lv0 = sd0 * 4 + cV;
    const int lsv0 = lv0 ^ ((lv0 >> 3) & 3);
    const int lv1 = sd0 * 4 + cV + 1;
    const int lsv1 = lv1 ^ ((lv1 >> 3) & 3);

    float m_[2][2] = {{-1e30f, -1e30f}, {-1e30f, -1e30f}};
    float l_[2][2] = {{0.f, 0.f}, {0.f, 0.f}};
    float acc[2][8][4];
#pragma unroll
    for (int mt = 0; mt < 2; ++mt)
#pragma unroll
        for (int nt = 0; nt < 8; ++nt)
#pragma unroll
            for (int i = 0; i < 4; ++i) acc[mt][nt][i] = 0.f;

    float4 kreg[8], vreg[8];

#pragma unroll
    for (int it = 0; it < 4; ++it) {
        int jg = ((tid & 3) + it * 4) * 4;
        kreg[2 * it]     = *(const float4*)(kb0 + jg);
        kreg[2 * it + 1] = *(const float4*)(kb1 + jg);
    }
#pragma unroll
    for (int it = 0; it < 8; ++it)
        vreg[it] = *(const float4*)(vbase + (size_t)it * 8 * ds);

#pragma unroll
    for (int it = 0; it < 4; ++it) {
        int jg = ((tid & 3) + it * 4) * 4;
        float fa[4] = {kreg[2*it].x, kreg[2*it].y, kreg[2*it].z, kreg[2*it].w};
        float fb[4] = {kreg[2*it+1].x, kreg[2*it+1].y, kreg[2*it+1].z, kreg[2*it+1].w};
#pragma unroll
        for (int e = 0; e < 4; ++e) {
            int j = jg + e;
            int tp = j >> 4, hi = (j >> 3) & 1, rK = j & 7;
            int lk = rK * 4 + cK;
            int lsk = lk ^ ((lk >> 3) & 3);
            sm[KF_OFF + (tp * 4 + kcK) * 128 + lsk * 4 + kwh + 2 * hi]
                = pack_h2(fa[e], fb[e]);
        }
    }
#pragma unroll
    for (int it = 0; it < 8; ++it) {
        int ntpV = it >> 1, hiV = it & 1;
        int ba = VF_OFF + (ntpV * 4 + kcV) * 128;
        sm[ba + lsv0 * 4 + vwh + 2 * hiV] = pack_h2(vreg[it].x, vreg[it].y);
        sm[ba + lsv1 * 4 + vwh + 2 * hiV] = pack_h2(vreg[it].z, vreg[it].w);
    }
    __syncthreads();

    const int QW = QF_OFF + wid * 1024;

    for (int t = 0; t < SEQ; t += 64) {
        const bool more = (t + 64) < SEQ;
        if (more) {
#pragma unroll
            for (int it = 0; it < 4; ++it) {
                int jg = ((tid & 3) + it * 4) * 4 + t + 64;
                kreg[2 * it]     = *(const float4*)(kb0 + jg);
                kreg[2 * it + 1] = *(const float4*)(kb1 + jg);
            }
        }

        float s[2][8][4];
#pragma unroll
        for (int mt = 0; mt < 2; ++mt)
#pragma unroll
            for (int nt = 0; nt < 8; ++nt)
#pragma unroll
                for (int i = 0; i < 4; ++i) s[mt][nt][i] = 0.f;

#pragma unroll
        for (int kc = 0; kc < 4; ++kc) {
            uint4 qa0 = *(const uint4*)&sm[QW + kc * 128 + lsw * 4];
            uint4 qa1 = *(const uint4*)&sm[QW + (4 + kc) * 128 + lsw * 4];
            uint32_t a0[4] = {qa0.x, qa0.y, qa0.z, qa0.w};
            uint32_t a1[4] = {qa1.x, qa1.y, qa1.z, qa1.w};
#pragma unroll
            for (int tp = 0; tp < 4; ++tp) {
                uint4 kf = *(const uint4*)&sm[KF_OFF + (tp * 4 + kc) * 128 + lsw * 4];
                mma_f16(s[0][2 * tp], a0, kf.x, kf.y);
                mma_f16(s[0][2 * tp + 1], a0, kf.z, kf.w);
                mma_f16(s[1][2 * tp], a1, kf.x, kf.y);
                mma_f16(s[1][2 * tp + 1], a1, kf.z, kf.w);
            }
        }

        __syncthreads();
        if (more) {
#pragma unroll
            for (int it = 0; it < 4; ++it) {
                int jg = ((tid & 3) + it * 4) * 4;
                float fa[4] = {kreg[2*it].x, kreg[2*it].y, kreg[2*it].z, kreg[2*it].w};
                float fb[4] = {kreg[2*it+1].x, kreg[2*it+1].y, kreg[2*it+1].z, kreg[2*it+1].w};
#pragma unroll
                for (int e = 0; e < 4; ++e) {
                    int j = jg + e;
                    int tp = j >> 4, hi = (j >> 3) & 1, rK = j & 7;
                    int lk = rK * 4 + cK;
                    int lsk = lk ^ ((lk >> 3) & 3);
                    sm[KF_OFF + (tp * 4 + kcK) * 128 + lsk * 4 + kwh + 2 * hi]
                        = pack_h2(fa[e], fb[e]);
                }
            }
#pragma unroll
            for (int it = 0; it < 8; ++it)
                vreg[it] = *(const float4*)(vbase + (size_t)it * 8 * ds + t + 64);
        }

#pragma unroll
        for (int mt = 0; mt < 2; ++mt) {
#pragma unroll
            for (int hh = 0; hh < 2; ++hh) {
                float mx = -1e30f;
#pragma unroll
                for (int nt = 0; nt < 8; ++nt)
                    mx = fmaxf(mx, fmaxf(s[mt][nt][2 * hh], s[mt][nt][2 * hh + 1]));
                mx = fmaxf(mx, __shfl_xor_sync(0xffffffffu, mx, 1));
                mx = fmaxf(mx, __shfl_xor_sync(0xffffffffu, mx, 2));
                float mn = fmaxf(m_[mt][hh], mx);
                float sc = exp2f(m_[mt][hh] - mn);
                float sum = 0.f;
#pragma unroll
                for (int nt = 0; nt < 8; ++nt) {
                    float e0 = exp2f(s[mt][nt][2 * hh] - mn);
                    float e1 = exp2f(s[mt][nt][2 * hh + 1] - mn);
                    s[mt][nt][2 * hh] = e0;
                    s[mt][nt][2 * hh + 1] = e1;
                    sum += e0 + e1;
                }
                sum += __shfl_xor_sync(0xffffffffu, sum, 1);
                sum += __shfl_xor_sync(0xffffffffu, sum, 2);
                l_[mt][hh] = l_[mt][hh] * sc + sum;
                m_[mt][hh] = mn;
#pragma unroll
                for (int nt = 0; nt < 8; ++nt) {
                    acc[mt][nt][2 * hh] *= sc;
                    acc[mt][nt][2 * hh + 1] *= sc;
                }
            }
        }

        uint32_t pa0[4][4], pa1[4][4];
#pragma unroll
        for (int kc = 0; kc < 4; ++kc) {
            pa0[kc][0] = pack_h2(s[0][2*kc][0],   s[0][2*kc][1]);
            pa0[kc][1] = pack_h2(s[0][2*kc][2],   s[0][2*kc][3]);
            pa0[kc][2] = pack_h2(s[0][2*kc+1][0], s[0][2*kc+1][1]);
            pa0[kc][3] = pack_h2(s[0][2*kc+1][2], s[0][2*kc+1][3]);
            pa1[kc][0] = pack_h2(s[1][2*kc][0],   s[1][2*kc][1]);
            pa1[kc][1] = pack_h2(s[1][2*kc][2],   s[1][2*kc][3]);
            pa1[kc][2] = pack_h2(s[1][2*kc+1][0], s[1][2*kc+1][1]);
            pa1[kc][3] = pack_h2(s[1][2*kc+1][2], s[1][2*kc+1][3]);
        }

#pragma unroll
        for (int kc = 0; kc < 4; ++kc) {
#pragma unroll
            for (int ntp = 0; ntp < 4; ++ntp) {
                uint4 vf = *(const uint4*)&sm[VF_OFF + (ntp * 4 + kc) * 128 + lsw * 4];
                mma_f16(acc[0][2 * ntp], pa0[kc], vf.x, vf.y);
                mma_f16(acc[0][2 * ntp + 1], pa0[kc], vf.z, vf.w);
                mma_f16(acc[1][2 * ntp], pa1[kc], vf.x, vf.y);
                mma_f16(acc[1][2 * ntp + 1], pa1[kc], vf.z, vf.w);
            }
        }

        __syncthreads();
        if (more) {
#pragma unroll
            for (int it = 0; it < 8; ++it) {
                int ntpV = it >> 1, hiV = it & 1;
                int ba = VF_OFF + (ntpV * 4 + kcV) * 128;
                sm[ba + lsv0 * 4 + vwh + 2 * hiV] = pack_h2(vreg[it].x, vreg[it].y);
                sm[ba + lsv1 * 4 + vwh + 2 * hiV] = pack_h2(vreg[it].z, vreg[it].w);
            }
        }
    }

    __syncthreads();
    float* Xs = (float*)sm;
#pragma unroll
    for (int mt = 0; mt < 2; ++mt) {
#pragma unroll
        for (int hh = 0; hh < 2; ++hh) {
            float inv = 1.f / l_[mt][hh];
            int q = wid * 32 + mt * 16 + r + 8 * hh;
#pragma unroll
            for (int nt = 0; nt < 8; ++nt) {
                int d0 = nt * 8 + 2 * c;
                Xs[d0 * XPITCH + q] = acc[mt][nt][2 * hh] * inv;
                Xs[(d0 + 1) * XPITCH + q] = acc[mt][nt][2 * hh + 1] * inv;
            }
        }
    }
    __syncthreads();
#pragma unroll
    for (int it = 0; it < 16; ++it) {
        int d = (tid >> 5) + it * 4;
        float4 v = *(const float4*)&Xs[d * XPITCH + lane * 4];
        *(float4*)(O + base + (size_t)d * ds + n0 + lane * 4) = v;
    }
}

// ---------------------------------------------------------------------------
// Launch: per-batch pipeline.
//   QKV(b0) -> attn(b0) -> Wm(b0)
//        \-> QKV(b1) runs under attn(b0); attn(b1) runs over Wm(b0)
// metadata order: query, key, value, Wq, bq, Wk, bk, Wv, bv, Wm, bm
// ---------------------------------------------------------------------------
extern "C" void kernel_launch(void* const* d_in, const int* in_sizes, int n_in,
                              void* d_out, int out_size)
{
    const float* query = (const float*)d_in[0];
    const float* key   = (const float*)d_in[1];
    const float* value = (const float*)d_in[2];
    const float* Wq = (const float*)d_in[3];
    const float* bq = (const float*)d_in[4];
    const float* Wk = (const float*)d_in[5];
    const float* bk = (const float*)d_in[6];
    const float* Wv = (const float*)d_in[7];
    const float* bv = (const float*)d_in[8];
    const float* Wm = (const float*)d_in[9];
    const float* bm = (const float*)d_in[10];
    float* out = (float*)d_out;

    float *Qp, *Kp, *Vp, *Xp;
    cudaGetSymbolAddress((void**)&Qp, g_Q);
    cudaGetSymbolAddress((void**)&Kp, g_K);
    cudaGetSymbolAddress((void**)&Vp, g_V);
    cudaGetSymbolAddress((void**)&Xp, g_X);

    static cudaStream_t s1, s2;
    static cudaEvent_t evRoot, e1a, e2a, e1b, e2b, eA0, eWm0;
    static bool init_done = false;
    if (!init_done) {
        cudaFuncSetAttribute(attn_mma3,
                             cudaFuncAttributeMaxDynamicSharedMemorySize,
                             ATTN_SMEM_B);
        cudaStreamCreateWithFlags(&s1, cudaStreamNonBlocking);
        cudaStreamCreateWithFlags(&s2, cudaStreamNonBlocking);
        cudaEventCreateWithFlags(&evRoot, cudaEventDisableTiming);
        cudaEventCreateWithFlags(&e1a, cudaEventDisableTiming);
        cudaEventCreateWithFlags(&e2a, cudaEventDisableTiming);
        cudaEventCreateWithFlags(&e1b, cudaEventDisableTiming);
        cudaEventCreateWithFlags(&e2b, cudaEventDisableTiming);
        cudaEventCreateWithFlags(&eA0, cudaEventDisableTiming);
        cudaEventCreateWithFlags(&eWm0, cudaEventDisableTiming);
        init_done = true;
    }

    const size_t boff = (size_t)DMODEL * SEQ;
    dim3 gGemm(SEQ / 128, DMODEL / 128, 1);     // (16, 8) per batch
    dim3 bGemm(256);
    dim3 gAttn(SEQ / 128, HEADS);               // (16, 16) per batch

    // Fork
    cudaEventRecord(evRoot, 0);
    cudaStreamWaitEvent(s1, evRoot, 0);
    cudaStreamWaitEvent(s2, evRoot, 0);

    // Batch-0 projections (3-way concurrent)
    gemm_mma_h<<<gGemm, bGemm, 0, 0>>>(Wq, query, bq, Qp);
    gemm_mma_h<<<gGemm, bGemm, 0, s1>>>(Wk, key, bk, Kp);
    cudaEventRecord(e1a, s1);
    gemm_mma_h<<<gGemm, bGemm, 0, s2>>>(Wv, value, bv, Vp);
    cudaEventRecord(e2a, s2);

    // Batch-1 projections queued behind them on the side streams
    gemm_mma_h<<<gGemm, bGemm, 0, s1>>>(Wq, query + boff, bq, Qp + boff);
    gemm_mma_h<<<gGemm, bGemm, 0, s1>>>(Wk, key + boff, bk, Kp + boff);
    cudaEventRecord(e1b, s1);
    gemm_mma_h<<<gGemm, bGemm, 0, s2>>>(Wv, value + boff, bv, Vp + boff);
    cudaEventRecord(e2b, s2);

    // attn(b0) — runs concurrently with the b1 projections
    cudaStreamWaitEvent(0, e1a, 0);
    cudaStreamWaitEvent(0, e2a, 0);
    attn_mma3<<<gAttn, 128, ATTN_SMEM_B>>>(Qp, Kp, Vp, Xp);
    cudaEventRecord(eA0, 0);

    // Wm(b0) on s2 — runs concurrently with attn(b1)
    cudaStreamWaitEvent(s2, eA0, 0);
    gemm_mma_h<<<gGemm, bGemm, 0, s2>>>(Wm, Xp, bm, out);
    cudaEventRecord(eWm0, s2);

    // attn(b1)
    cudaStreamWaitEvent(0, e1b, 0);
    cudaStreamWaitEvent(0, e2b, 0);
    attn_mma3<<<gAttn, 128, ATTN_SMEM_B>>>(Qp + boff, Kp + boff, Vp + boff,
                                           Xp + boff);

    // Wm(b1) + final join
    cudaStreamWaitEvent(0, eWm0, 0);
    gemm_mma_h<<<gGemm, bGemm, 0, 0>>>(Wm, Xp + boff, bm, out + boff);
}

// round 17
// speedup vs baseline: 1.1070x; 1.1070x over previous
#include <cuda_runtime.h>
#include <cuda_fp16.h>
#include <cstdint>
#include <math.h>

// Problem constants
#define BATCH 2
#define DMODEL 1024
#define SEQ 2048
#define HEADS 16
#define HDIM 64

// Scratch (allocation-free rule: __device__ globals)
__device__ float g_Q[BATCH * DMODEL * SEQ];
__device__ float g_K[BATCH * DMODEL * SEQ];
__device__ float g_V[BATCH * DMODEL * SEQ];
__device__ float g_X[BATCH * DMODEL * SEQ];

// ===========================================================================
// Helpers
// ===========================================================================
__device__ __forceinline__ uint32_t pack_h2(float lo, float hi) {
    __half2 h = __floats2half2_rn(lo, hi);
    return *reinterpret_cast<uint32_t*>(&h);
}

// D += A * B  (m16n8k16, fp16 inputs, fp32 accum). A row-major, B "col".
__device__ __forceinline__ void mma_f16(float d[4], const uint32_t a[4],
                                        uint32_t b0, uint32_t b1) {
    asm volatile(
        "mma.sync.aligned.m16n8k16.row.col.f32.f16.f16.f32 "
        "{%0,%1,%2,%3}, {%4,%5,%6,%7}, {%8,%9}, {%0,%1,%2,%3};\n"
        : "+f"(d[0]), "+f"(d[1]), "+f"(d[2]), "+f"(d[3])
        : "r"(a[0]), "r"(a[1]), "r"(a[2]), "r"(a[3]), "r"(b0), "r"(b1));
}

// ===========================================================================
// GEMM v5 (fp16 m16n8k16, software-pipelined):
//   C[m][n] = sum_k A[m][k] * X[k][n] + bias[m]   (one batch slice)
// Block 128x128, 8 warps (64x32 warp tiles). K-chunks of 32, double-buffered
// fp16x2 smem, register prefetch of chunk kt+1 issued before compute of kt,
// ONE barrier per chunk. k16-step order identical to v4 (bitwise-same C).
//   As[m][kp] pitch 20 (128 x 16 kp): fragment reads conflict-free
//   Bs[kp][n] pitch 136 (16 x 128):   fragment reads conflict-free
// ===========================================================================
#define AP 20
#define BP 136
#define ABUF (128 * AP)     // words per A stage
#define BBUF (16 * BP)      // words per B stage

__device__ __forceinline__ void gemm_core(
    const float* __restrict__ A, const float* __restrict__ Xb,
    const float* __restrict__ bias, float* __restrict__ Cb,
    uint32_t* __restrict__ As, uint32_t* __restrict__ Bs)
{
    const int tid = threadIdx.x;
    const int lane = tid & 31;
    const int wid = tid >> 5;
    const int wm = (wid >> 2) * 64;
    const int wn = (wid & 3) * 32;
    const int r = lane >> 2, c = lane & 3;
    const int row0 = blockIdx.y * 128, col0 = blockIdx.x * 128;

    // staging thread constants
    const int m_base = tid >> 3;          // 0..31 (A rows m_base + it*32)
    const int k4f = (tid & 7) << 2;       // A k element base
    const int kp2 = (tid & 7) << 1;       // A kp word base
    const int kp_base = tid >> 5;         // 0..7 (B kp rows kp_base + it*8)
    const int n4 = lane << 2;             // B n element base

    uint32_t* As1 = As + ABUF;
    uint32_t* Bs1 = Bs + BBUF;

    float acc[4][4][4];
#pragma unroll
    for (int mt = 0; mt < 4; mt++)
#pragma unroll
        for (int nt = 0; nt < 4; nt++)
#pragma unroll
            for (int i = 0; i < 4; i++) acc[mt][nt][i] = 0.f;

    float4 pa[4], pba[2], pbb[2];

#define GLOAD(k0_) do {                                                       \
    _Pragma("unroll")                                                         \
    for (int it = 0; it < 4; ++it)                                            \
        pa[it] = *(const float4*)(A + (size_t)(row0 + m_base + it * 32)       \
                                       * DMODEL + (k0_) + k4f);               \
    _Pragma("unroll")                                                         \
    for (int it = 0; it < 2; ++it) {                                          \
        const float* x0 = Xb + (size_t)((k0_) + 2 * (kp_base + it * 8)) * SEQ \
                             + col0 + n4;                                     \
        pba[it] = *(const float4*)x0;                                         \
        pbb[it] = *(const float4*)(x0 + SEQ);                                 \
    }                                                                         \
} while (0)

#define GSTORE(bufA, bufB) do {                                               \
    _Pragma("unroll")                                                         \
    for (int it = 0; it < 4; ++it) {                                          \
        (bufA)[(m_base + it * 32) * AP + kp2]     = pack_h2(pa[it].x, pa[it].y); \
        (bufA)[(m_base + it * 32) * AP + kp2 + 1] = pack_h2(pa[it].z, pa[it].w); \
    }                                                                         \
    _Pragma("unroll")                                                         \
    for (int it = 0; it < 2; ++it) {                                          \
        uint32_t* bp = (bufB) + (kp_base + it * 8) * BP + n4;                 \
        bp[0] = pack_h2(pba[it].x, pbb[it].x);                                \
        bp[1] = pack_h2(pba[it].y, pbb[it].y);                                \
        bp[2] = pack_h2(pba[it].z, pbb[it].z);                                \
        bp[3] = pack_h2(pba[it].w, pbb[it].w);                                \
    }                                                                         \
} while (0)

#define GCOMPUTE(bufA, bufB) do {                                             \
    _Pragma("unroll")                                                         \
    for (int ks = 0; ks < 2; ++ks) {                                          \
        uint32_t bf[4][2];                                                    \
        _Pragma("unroll")                                                     \
        for (int nt = 0; nt < 4; ++nt) {                                      \
            int nc = wn + nt * 8 + r;                                         \
            bf[nt][0] = (bufB)[(ks * 8 + c) * BP + nc];                       \
            bf[nt][1] = (bufB)[(ks * 8 + c + 4) * BP + nc];                   \
        }                                                                     \
        _Pragma("unroll")                                                     \
        for (int mt = 0; mt < 4; ++mt) {                                      \
            int mr = wm + mt * 16 + r;                                        \
            uint32_t af[4];                                                   \
            af[0] = (bufA)[mr * AP + ks * 8 + c];                             \
            af[1] = (bufA)[(mr + 8) * AP + ks * 8 + c];                       \
            af[2] = (bufA)[mr * AP + ks * 8 + c + 4];                         \
            af[3] = (bufA)[(mr + 8) * AP + ks * 8 + c + 4];                   \
            _Pragma("unroll")                                                 \
            for (int nt = 0; nt < 4; ++nt)                                    \
                mma_f16(acc[mt][nt], af, bf[nt][0], bf[nt][1]);               \
        }                                                                     \
    }                                                                         \
} while (0)

    // Prologue: chunk 0 -> buffer 0
    GLOAD(0);
    GSTORE(As, Bs);
    __syncthreads();

    // 32 chunks, processed 2 per iteration (even->As, odd->As1)
#pragma unroll 1
    for (int kt = 0; kt < 32; kt += 2) {
        GLOAD((kt + 1) * 32);
        GCOMPUTE(As, Bs);
        GSTORE(As1, Bs1);
        __syncthreads();
        if (kt + 2 < 32) {
            GLOAD((kt + 2) * 32);
            GCOMPUTE(As1, Bs1);
            GSTORE(As, Bs);
        } else {
            GCOMPUTE(As1, Bs1);
        }
        __syncthreads();
    }

#undef GLOAD
#undef GSTORE
#undef GCOMPUTE

    // Epilogue: fused bias, direct float2 stores
#pragma unroll
    for (int mt = 0; mt < 4; ++mt) {
        int r0 = row0 + wm + mt * 16 + r;
        float bv0 = __ldg(bias + r0);
        float bv1 = __ldg(bias + r0 + 8);
#pragma unroll
        for (int nt = 0; nt < 4; ++nt) {
            int c0 = col0 + wn + nt * 8 + c * 2;
            float2 v0 = make_float2(acc[mt][nt][0] + bv0, acc[mt][nt][1] + bv0);
            float2 v1 = make_float2(acc[mt][nt][2] + bv1, acc[mt][nt][3] + bv1);
            *(float2*)(Cb + (size_t)r0 * SEQ + c0) = v0;
            *(float2*)(Cb + (size_t)(r0 + 8) * SEQ + c0) = v1;
        }
    }
}

// Fat QKV kernel: blockIdx.z = proj*2 + batch  (grid z = 6)
__global__ __launch_bounds__(256, 2) void gemm_qkv(
    const float* __restrict__ Wq, const float* __restrict__ Wk,
    const float* __restrict__ Wv,
    const float* __restrict__ query, const float* __restrict__ key,
    const float* __restrict__ value,
    const float* __restrict__ bq, const float* __restrict__ bk,
    const float* __restrict__ bv,
    float* __restrict__ Qp, float* __restrict__ Kp, float* __restrict__ Vp)
{
    __shared__ uint32_t As[2 * ABUF];
    __shared__ uint32_t Bs[2 * BBUF];
    const int z = blockIdx.z;
    const size_t off = (size_t)(z & 1) * DMODEL * SEQ;
    const int pj = z >> 1;
    const float *A, *X, *bi;
    float* C;
    if (pj == 0)      { A = Wq; X = query + off; bi = bq; C = g_Q + off; }
    else if (pj == 1) { A = Wk; X = key + off;   bi = bk; C = g_K + off; }
    else              { A = Wv; X = value + off; bi = bv; C = g_V + off; }
    (void)Qp; (void)Kp; (void)Vp;
    gemm_core(A, X, bi, C, As, Bs);
}

// Output projection: blockIdx.z = batch (grid z = 2)
__global__ __launch_bounds__(256, 2) void gemm_out(
    const float* __restrict__ Wm, const float* __restrict__ Xp,
    const float* __restrict__ bm, float* __restrict__ out)
{
    __shared__ uint32_t As[2 * ABUF];
    __shared__ uint32_t Bs[2 * BBUF];
    const size_t off = (size_t)blockIdx.z * DMODEL * SEQ;
    gemm_core(Wm, Xp + off, bm, out + off, As, Bs);
}

// ===========================================================================
// Flash attention v3 (R15 verbatim): fp16 m16n8k16, register-resident P.
// Grid (16 qtiles, 32 bh).
// ===========================================================================
#define QF_OFF 0
#define KF_OFF 4096
#define VF_OFF 6144
#define ATTN_SMEM_B (8448 * 4)
#define XPITCH 132
#define QSCALE 0.1803368801111204f   // 0.125 * log2(e)

__global__ __launch_bounds__(128, 2) void attn_mma3(
    const float* __restrict__ Q, const float* __restrict__ K,
    const float* __restrict__ V, float* __restrict__ O)
{
    extern __shared__ uint32_t sm[];

    const int tid = threadIdx.x;
    const int lane = tid & 31, wid = tid >> 5;
    const int r = lane >> 2, c = lane & 3;
    const int lsw = lane ^ ((lane >> 3) & 3);

    const int bh = blockIdx.y;
    const int b = bh >> 4, h = bh & 15;
    const int n0 = blockIdx.x * 128;
    const size_t base = (size_t)b * DMODEL * SEQ + (size_t)h * SEQ;
    const size_t ds = (size_t)HEADS * SEQ;

    // ---------------- Stage Q (fp16x2 A-fragment-major, scaled) ------------
    {
        const int q_dp = tid >> 2;
        const int cQ = q_dp & 3, ahalf = (q_dp >> 2) & 1, kcQ = q_dp >> 3;
        const float* q0 = Q + base + (size_t)(2 * q_dp) * ds + n0;
        const float* q1 = q0 + ds;
#pragma unroll
        for (int it = 0; it < 8; ++it) {
            int qg = ((tid & 3) + it * 4) * 4;
            float4 va = *(const float4*)(q0 + qg);
            float4 vb = *(const float4*)(q1 + qg);
            float fa[4] = {va.x, va.y, va.z, va.w};
            float fb[4] = {vb.x, vb.y, vb.z, vb.w};
#pragma unroll
            for (int e = 0; e < 4; ++e) {
                int qloc = qg + e;
                int wq = qloc >> 5, mtq = (qloc >> 4) & 1;
                int rhq = (qloc >> 3) & 1, rQ = qloc & 7;
                int lq = rQ * 4 + cQ;
                int lsq = lq ^ ((lq >> 3) & 3);
                sm[QF_OFF + wq * 1024 + (mtq * 4 + kcQ) * 128 + lsq * 4
                   + rhq + 2 * ahalf] = pack_h2(fa[e] * QSCALE, fb[e] * QSCALE);
            }
        }
    }

    const int k_dp = tid >> 2;
    const int cK = k_dp & 3, kwh = (k_dp >> 2) & 1, kcK = k_dp >> 3;
    const float* kb0 = K + base + (size_t)(2 * k_dp) * ds;
    const float* kb1 = kb0 + ds;

    const int sd0 = tid >> 4;
    const int sj0 = (tid & 15) * 4;
    const float* vbase = V + base + (size_t)sd0 * ds + sj0;
    const int jp0 = sj0 >> 1;
    const int kcV = jp0 >> 3, jplV = jp0 & 7;
    const int cV = jplV & 3, vwh = (jplV >> 2) & 1;
    const int lv0 = sd0 * 4 + cV;
    const int lsv0 = lv0 ^ ((lv0 >> 3) & 3);
    const int lv1 = sd0 * 4 + cV + 1;
    const int lsv1 = lv1 ^ ((lv1 >> 3) & 3);

    float m_[2][2] = {{-1e30f, -1e30f}, {-1e30f, -1e30f}};
    float l_[2][2] = {{0.f, 0.f}, {0.f, 0.f}};
    float acc[2][8][4];
#pragma unroll
    for (int mt = 0; mt < 2; ++mt)
#pragma unroll
        for (int nt = 0; nt < 8; ++nt)
#pragma unroll
            for (int i = 0; i < 4; ++i) acc[mt][nt][i] = 0.f;

    float4 kreg[8], vreg[8];

#pragma unroll
    for (int it = 0; it < 4; ++it) {
        int jg = ((tid & 3) + it * 4) * 4;
        kreg[2 * it]     = *(const float4*)(kb0 + jg);
        kreg[2 * it + 1] = *(const float4*)(kb1 + jg);
    }
#pragma unroll
    for (int it = 0; it < 8; ++it)
        vreg[it] = *(const float4*)(vbase + (size_t)it * 8 * ds);

#pragma unroll
    for (int it = 0; it < 4; ++it) {
        int jg = ((tid & 3) + it * 4) * 4;
        float fa[4] = {kreg[2*it].x, kreg[2*it].y, kreg[2*it].z, kreg[2*it].w};
        float fb[4] = {kreg[2*it+1].x, kreg[2*it+1].y, kreg[2*it+1].z, kreg[2*it+1].w};
#pragma unroll
        for (int e = 0; e < 4; ++e) {
            int j = jg + e;
            int tp = j >> 4, hi = (j >> 3) & 1, rK = j & 7;
            int lk = rK * 4 + cK;
            int lsk = lk ^ ((lk >> 3) & 3);
            sm[KF_OFF + (tp * 4 + kcK) * 128 + lsk * 4 + kwh + 2 * hi]
                = pack_h2(fa[e], fb[e]);
        }
    }
#pragma unroll
    for (int it = 0; it < 8; ++it) {
        int ntpV = it >> 1, hiV = it & 1;
        int ba = VF_OFF + (ntpV * 4 + kcV) * 128;
        sm[ba + lsv0 * 4 + vwh + 2 * hiV] = pack_h2(vreg[it].x, vreg[it].y);
        sm[ba + lsv1 * 4 + vwh + 2 * hiV] = pack_h2(vreg[it].z, vreg[it].w);
    }
    __syncthreads();

    const int QW = QF_OFF + wid * 1024;

    for (int t = 0; t < SEQ; t += 64) {
        const bool more = (t + 64) < SEQ;
        if (more) {
#pragma unroll
            for (int it = 0; it < 4; ++it) {
                int jg = ((tid & 3) + it * 4) * 4 + t + 64;
                kreg[2 * it]     = *(const float4*)(kb0 + jg);
                kreg[2 * it + 1] = *(const float4*)(kb1 + jg);
            }
        }

        float s[2][8][4];
#pragma unroll
        for (int mt = 0; mt < 2; ++mt)
#pragma unroll
            for (int nt = 0; nt < 8; ++nt)
#pragma unroll
                for (int i = 0; i < 4; ++i) s[mt][nt][i] = 0.f;

#pragma unroll
        for (int kc = 0; kc < 4; ++kc) {
            uint4 qa0 = *(const uint4*)&sm[QW + kc * 128 + lsw * 4];
            uint4 qa1 = *(const uint4*)&sm[QW + (4 + kc) * 128 + lsw * 4];
            uint32_t a0[4] = {qa0.x, qa0.y, qa0.z, qa0.w};
            uint32_t a1[4] = {qa1.x, qa1.y, qa1.z, qa1.w};
#pragma unroll
            for (int tp = 0; tp < 4; ++tp) {
                uint4 kf = *(const uint4*)&sm[KF_OFF + (tp * 4 + kc) * 128 + lsw * 4];
                mma_f16(s[0][2 * tp], a0, kf.x, kf.y);
                mma_f16(s[0][2 * tp + 1], a0, kf.z, kf.w);
                mma_f16(s[1][2 * tp], a1, kf.x, kf.y);
                mma_f16(s[1][2 * tp + 1], a1, kf.z, kf.w);
            }
        }

        __syncthreads();
        if (more) {
#pragma unroll
            for (int it = 0; it < 4; ++it) {
                int jg = ((tid & 3) + it * 4) * 4;
                float fa[4] = {kreg[2*it].x, kreg[2*it].y, kreg[2*it].z, kreg[2*it].w};
                float fb[4] = {kreg[2*it+1].x, kreg[2*it+1].y, kreg[2*it+1].z, kreg[2*it+1].w};
#pragma unroll
                for (int e = 0; e < 4; ++e) {
                    int j = jg + e;
                    int tp = j >> 4, hi = (j >> 3) & 1, rK = j & 7;
                    int lk = rK * 4 + cK;
                    int lsk = lk ^ ((lk >> 3) & 3);
                    sm[KF_OFF + (tp * 4 + kcK) * 128 + lsk * 4 + kwh + 2 * hi]
                        = pack_h2(fa[e], fb[e]);
                }
            }
#pragma unroll
            for (int it = 0; it < 8; ++it)
                vreg[it] = *(const float4*)(vbase + (size_t)it * 8 * ds + t + 64);
        }

#pragma unroll
        for (int mt = 0; mt < 2; ++mt) {
#pragma unroll
            for (int hh = 0; hh < 2; ++hh) {
                float mx = -1e30f;
#pragma unroll
                for (int nt = 0; nt < 8; ++nt)
                    mx = fmaxf(mx, fmaxf(s[mt][nt][2 * hh], s[mt][nt][2 * hh + 1]));
                mx = fmaxf(mx, __shfl_xor_sync(0xffffffffu, mx, 1));
                mx = fmaxf(mx, __shfl_xor_sync(0xffffffffu, mx, 2));
                float mn = fmaxf(m_[mt][hh], mx);
                float sc = exp2f(m_[mt][hh] - mn);
                float sum = 0.f;
#pragma unroll
                for (int nt = 0; nt < 8; ++nt) {
                    float e0 = exp2f(s[mt][nt][2 * hh] - mn);
                    float e1 = exp2f(s[mt][nt][2 * hh + 1] - mn);
                    s[mt][nt][2 * hh] = e0;
                    s[mt][nt][2 * hh + 1] = e1;
                    sum += e0 + e1;
                }
                sum += __shfl_xor_sync(0xffffffffu, sum, 1);
                sum += __shfl_xor_sync(0xffffffffu, sum, 2);
                l_[mt][hh] = l_[mt][hh] * sc + sum;
                m_[mt][hh] = mn;
#pragma unroll
                for (int nt = 0; nt < 8; ++nt) {
                    acc[mt][nt][2 * hh] *= sc;
                    acc[mt][nt][2 * hh + 1] *= sc;
                }
            }
        }

        uint32_t pa0[4][4], pa1[4][4];
#pragma unroll
        for (int kc = 0; kc < 4; ++kc) {
            pa0[kc][0] = pack_h2(s[0][2*kc][0],   s[0][2*kc][1]);
            pa0[kc][1] = pack_h2(s[0][2*kc][2],   s[0][2*kc][3]);
            pa0[kc][2] = pack_h2(s[0][2*kc+1][0], s[0][2*kc+1][1]);
            pa0[kc][3] = pack_h2(s[0][2*kc+1][2], s[0][2*kc+1][3]);
            pa1[kc][0] = pack_h2(s[1][2*kc][0],   s[1][2*kc][1]);
            pa1[kc][1] = pack_h2(s[1][2*kc][2],   s[1][2*kc][3]);
            pa1[kc][2] = pack_h2(s[1][2*kc+1][0], s[1][2*kc+1][1]);
            pa1[kc][3] = pack_h2(s[1][2*kc+1][2], s[1][2*kc+1][3]);
        }

#pragma unroll
        for (int kc = 0; kc < 4; ++kc) {
#pragma unroll
            for (int ntp = 0; ntp < 4; ++ntp) {
                uint4 vf = *(const uint4*)&sm[VF_OFF + (ntp * 4 + kc) * 128 + lsw * 4];
                mma_f16(acc[0][2 * ntp], pa0[kc], vf.x, vf.y);
                mma_f16(acc[0][2 * ntp + 1], pa0[kc], vf.z, vf.w);
                mma_f16(acc[1][2 * ntp], pa1[kc], vf.x, vf.y);
                mma_f16(acc[1][2 * ntp + 1], pa1[kc], vf.z, vf.w);
            }
        }

        __syncthreads();
        if (more) {
#pragma unroll
            for (int it = 0; it < 8; ++it) {
                int ntpV = it >> 1, hiV = it & 1;
                int ba = VF_OFF + (ntpV * 4 + kcV) * 128;
                sm[ba + lsv0 * 4 + vwh + 2 * hiV] = pack_h2(vreg[it].x, vreg[it].y);
                sm[ba + lsv1 * 4 + vwh + 2 * hiV] = pack_h2(vreg[it].z, vreg[it].w);
            }
        }
    }

    __syncthreads();
    float* Xs = (float*)sm;
#pragma unroll
    for (int mt = 0; mt < 2; ++mt) {
#pragma unroll
        for (int hh = 0; hh < 2; ++hh) {
            float inv = 1.f / l_[mt][hh];
            int q = wid * 32 + mt * 16 + r + 8 * hh;
#pragma unroll
            for (int nt = 0; nt < 8; ++nt) {
                int d0 = nt * 8 + 2 * c;
                Xs[d0 * XPITCH + q] = acc[mt][nt][2 * hh] * inv;
                Xs[(d0 + 1) * XPITCH + q] = acc[mt][nt][2 * hh + 1] * inv;
            }
        }
    }
    __syncthreads();
#pragma unroll
    for (int it = 0; it < 16; ++it) {
        int d = (tid >> 5) + it * 4;
        float4 v = *(const float4*)&Xs[d * XPITCH + lane * 4];
        *(float4*)(O + base + (size_t)d * ds + n0 + lane * 4) = v;
    }
}

// ---------------------------------------------------------------------------
// Launch.  metadata order: query, key, value, Wq, bq, Wk, bk, Wv, bv, Wm, bm
// Single-stream DAG: fat QKV (z=6) -> attn (batched) -> Wm (z=2).
// ---------------------------------------------------------------------------
extern "C" void kernel_launch(void* const* d_in, const int* in_sizes, int n_in,
                              void* d_out, int out_size)
{
    const float* query = (const float*)d_in[0];
    const float* key   = (const float*)d_in[1];
    const float* value = (const float*)d_in[2];
    const float* Wq = (const float*)d_in[3];
    const float* bq = (const float*)d_in[4];
    const float* Wk = (const float*)d_in[5];
    const float* bk = (const float*)d_in[6];
    const float* Wv = (const float*)d_in[7];
    const float* bv = (const float*)d_in[8];
    const float* Wm = (const float*)d_in[9];
    const float* bm = (const float*)d_in[10];
    float* out = (float*)d_out;

    float *Qp, *Kp, *Vp, *Xp;
    cudaGetSymbolAddress((void**)&Qp, g_Q);
    cudaGetSymbolAddress((void**)&Kp, g_K);
    cudaGetSymbolAddress((void**)&Vp, g_V);
    cudaGetSymbolAddress((void**)&Xp, g_X);

    static bool init_done = false;
    if (!init_done) {
        cudaFuncSetAttribute(attn_mma3,
                             cudaFuncAttributeMaxDynamicSharedMemorySize,
                             ATTN_SMEM_B);
        init_done = true;
    }

    dim3 bGemm(256);
    dim3 gQKV(SEQ / 128, DMODEL / 128, 6);   // (16, 8, 6)
    dim3 gOut(SEQ / 128, DMODEL / 128, 2);   // (16, 8, 2)
    dim3 gAttn(SEQ / 128, BATCH * HEADS);    // (16, 32)

    gemm_qkv<<<gQKV, bGemm>>>(Wq, Wk, Wv, query, key, value,
                              bq, bk, bv, Qp, Kp, Vp);
    attn_mma3<<<gAttn, 128, ATTN_SMEM_B>>>(Qp, Kp, Vp, Xp);
    gemm_out<<<gOut, bGemm>>>(Wm, Xp, bm, out);
}